// round 4
// baseline (speedup 1.0000x reference)
#include <cuda_runtime.h>
#include <math.h>

typedef unsigned long long ull;

// B=32, T=1024, C=1024, J=2048. One persistent kernel, 128 blocks x 512 thr.
// fp32 math, packed pairwise over batch (b, b+16) via fma.rn.f32x2.

#define BB 32
#define CC 1024
#define TT 1024
#define NBLK 128

// ---- packed f32x2 helpers ----
#define FMA2(d, a, b) asm("fma.rn.f32x2 %0, %1, %2, %0;" : "+l"(d) : "l"(a), "l"(b))
#define ADD2(d, a, b) asm("add.rn.f32x2 %0, %1, %2;" : "=l"(d) : "l"(a), "l"(b))
#define MUL2(d, a, b) asm("mul.rn.f32x2 %0, %1, %2;" : "=l"(d) : "l"(a), "l"(b))

__device__ __forceinline__ ull pack2(float lo, float hi) {
    ull d;
    asm("mov.b64 %0, {%1, %2};" : "=l"(d)
        : "r"(__float_as_uint(lo)), "r"(__float_as_uint(hi)));
    return d;
}
__device__ __forceinline__ ull pdup(float v) {
    ull d;
    asm("mov.b64 %0, {%1, %1};" : "=l"(d) : "r"(__float_as_uint(v)));
    return d;
}
__device__ __forceinline__ void unpack2(ull d, float& lo, float& hi) {
    unsigned a, b;
    asm("mov.b64 {%0, %1}, %2;" : "=r"(a), "=r"(b) : "l"(d));
    lo = __uint_as_float(a);
    hi = __uint_as_float(b);
}

// ---- scratch (device globals) ----
__device__ __align__(16) float g_h[BB * CC];          // h[b][c]
__device__ __align__(16) ull g_yp[8][2048 * 16];      // GEMM1 partials [kc][j*16+bp]
__device__ __align__(16) ull g_y2p[16][1024 * 16];    // GEMM2 partials [kc2][n*16+bp]

// ---- grid barrier ----
__device__ unsigned g_count = 0;
__device__ volatile unsigned g_gen = 0;

__device__ __forceinline__ void gbar() {
    __syncthreads();
    if (threadIdx.x == 0) {
        __threadfence();
        unsigned gen = g_gen;
        if (atomicAdd(&g_count, 1u) == NBLK - 1u) {
            atomicExch(&g_count, 0u);
            __threadfence();
            g_gen = gen + 1u;
        } else {
            while (g_gen == gen) __nanosleep(32);
        }
        __threadfence();
    }
    __syncthreads();
}

// smem (ull units): zs [16][258] at 0 (phase C uses [16][130]); wp 2x[128][34] at 4128
#define WOFF 4128
#define WSTR (128 * 34)
#define SMEM_ULL (WOFF + 2 * WSTR)   // 12832 ull = 102656 B

// Inner GEMM: acc[jj][bpi] (f32x2 over b-pair), 32-K stages, double-buffered W.
template <int NKS, int ZROW>
__device__ __forceinline__ void gemm_core(const float* __restrict__ wrow, ull* smU,
                                          ull acc[2][2], int tid, int tx, int ty) {
    ull* zs = smU;
    ull* wp = smU + WOFF;
    const int jf = tid >> 2, kq = (tid & 3) * 8;
    const float* wsrc = wrow + (size_t)jf * 2048 + kq;

    {   // stage-0 weight fill (duplicated packs)
        float4 f0 = *(const float4*)wsrc;
        float4 f1 = *(const float4*)(wsrc + 4);
        ull* wdst = wp + jf * 34 + kq;
        ulonglong2 u;
        u.x = pdup(f0.x); u.y = pdup(f0.y); *(ulonglong2*)(wdst)     = u;
        u.x = pdup(f0.z); u.y = pdup(f0.w); *(ulonglong2*)(wdst + 2) = u;
        u.x = pdup(f1.x); u.y = pdup(f1.y); *(ulonglong2*)(wdst + 4) = u;
        u.x = pdup(f1.z); u.y = pdup(f1.w); *(ulonglong2*)(wdst + 6) = u;
    }
    __syncthreads();

    int buf = 0;
#pragma unroll 1
    for (int ks = 0; ks < NKS; ks++) {
        float4 f0, f1;
        if (ks + 1 < NKS) {
            f0 = *(const float4*)(wsrc + (ks + 1) * 32);
            f1 = *(const float4*)(wsrc + (ks + 1) * 32 + 4);
        }
        const ull* w0 = wp + buf * WSTR + ty * 34;
        const ull* w1 = w0 + 64 * 34;
        const ull* z0 = zs + tx * ZROW + ks * 32;
        const ull* z1 = z0 + 8 * ZROW;
#pragma unroll
        for (int kk = 0; kk < 8; kk++) {
            ulonglong2 wa0 = *(const ulonglong2*)(w0 + kk * 4);
            ulonglong2 wb0 = *(const ulonglong2*)(w0 + kk * 4 + 2);
            ulonglong2 wa1 = *(const ulonglong2*)(w1 + kk * 4);
            ulonglong2 wb1 = *(const ulonglong2*)(w1 + kk * 4 + 2);
            ulonglong2 za0 = *(const ulonglong2*)(z0 + kk * 4);
            ulonglong2 zb0 = *(const ulonglong2*)(z0 + kk * 4 + 2);
            ulonglong2 za1 = *(const ulonglong2*)(z1 + kk * 4);
            ulonglong2 zb1 = *(const ulonglong2*)(z1 + kk * 4 + 2);
            FMA2(acc[0][0], wa0.x, za0.x); FMA2(acc[0][0], wa0.y, za0.y);
            FMA2(acc[0][0], wb0.x, zb0.x); FMA2(acc[0][0], wb0.y, zb0.y);
            FMA2(acc[0][1], wa0.x, za1.x); FMA2(acc[0][1], wa0.y, za1.y);
            FMA2(acc[0][1], wb0.x, zb1.x); FMA2(acc[0][1], wb0.y, zb1.y);
            FMA2(acc[1][0], wa1.x, za0.x); FMA2(acc[1][0], wa1.y, za0.y);
            FMA2(acc[1][0], wb1.x, zb0.x); FMA2(acc[1][0], wb1.y, zb0.y);
            FMA2(acc[1][1], wa1.x, za1.x); FMA2(acc[1][1], wa1.y, za1.y);
            FMA2(acc[1][1], wb1.x, zb1.x); FMA2(acc[1][1], wb1.y, zb1.y);
        }
        if (ks + 1 < NKS) {
            ull* wdst = wp + (buf ^ 1) * WSTR + jf * 34 + kq;
            ulonglong2 u;
            u.x = pdup(f0.x); u.y = pdup(f0.y); *(ulonglong2*)(wdst)     = u;
            u.x = pdup(f0.z); u.y = pdup(f0.w); *(ulonglong2*)(wdst + 2) = u;
            u.x = pdup(f1.x); u.y = pdup(f1.y); *(ulonglong2*)(wdst + 4) = u;
            u.x = pdup(f1.z); u.y = pdup(f1.w); *(ulonglong2*)(wdst + 6) = u;
        }
        __syncthreads();
        buf ^= 1;
    }
}

__global__ void __launch_bounds__(512, 1)
k_main(const float* __restrict__ x, const float* __restrict__ Wa,
       const float* __restrict__ ba, const float* __restrict__ Wb,
       const float* __restrict__ bb, const float* __restrict__ gamma,
       const float* __restrict__ beta, float* __restrict__ out) {
    extern __shared__ ull smU[];
    const int bid = blockIdx.x, tid = threadIdx.x;
    const int tx = tid & 7, ty = tid >> 3;   // tx: b-pair groups, ty: j/n rows

    for (int i = bid * 512 + tid; i < BB * CC; i += NBLK * 512) g_h[i] = 0.0f;
    gbar();

    for (int t = 0; t < TT; t++) {
        // ========== Phase A: GEMM1 partial (16 jt x 8 kc; kc<4 -> h, else x) ==========
        {
            const int jt = bid & 15, kc = bid >> 4;
            // z fill: zs[bp][k] = (z[bp][k], z[bp+16][k]) packed
            {
                const int bp = tid >> 5, kq = (tid & 31) * 8;
                float4 a0, a1, b0, b1;
                if (kc < 4) {
                    const float* plo = g_h + bp * CC + kc * 256 + kq;
                    const float* phi = plo + 16 * CC;
                    a0 = __ldcg((const float4*)plo);
                    a1 = __ldcg((const float4*)(plo + 4));
                    b0 = __ldcg((const float4*)phi);
                    b1 = __ldcg((const float4*)(phi + 4));
                } else {
                    const float* plo = x + ((size_t)bp * TT + t) * CC + (kc - 4) * 256 + kq;
                    const float* phi = x + ((size_t)(bp + 16) * TT + t) * CC + (kc - 4) * 256 + kq;
                    a0 = *(const float4*)plo;
                    a1 = *(const float4*)(plo + 4);
                    b0 = *(const float4*)phi;
                    b1 = *(const float4*)(phi + 4);
                }
                ull* zdst = smU + bp * 258 + kq;
                ulonglong2 u;
                u.x = pack2(a0.x, b0.x); u.y = pack2(a0.y, b0.y); *(ulonglong2*)(zdst)     = u;
                u.x = pack2(a0.z, b0.z); u.y = pack2(a0.w, b0.w); *(ulonglong2*)(zdst + 2) = u;
                u.x = pack2(a1.x, b1.x); u.y = pack2(a1.y, b1.y); *(ulonglong2*)(zdst + 4) = u;
                u.x = pack2(a1.z, b1.z); u.y = pack2(a1.w, b1.w); *(ulonglong2*)(zdst + 6) = u;
            }
            ull acc[2][2] = {{0ull, 0ull}, {0ull, 0ull}};
            gemm_core<8, 258>(Wa + (size_t)(jt * 128) * 2048 + kc * 256, smU, acc, tid, tx, ty);
            const int jb = jt * 128 + ty;
            g_yp[kc][jb * 16 + tx]            = acc[0][0];
            g_yp[kc][jb * 16 + tx + 8]        = acc[0][1];
            g_yp[kc][(jb + 64) * 16 + tx]     = acc[1][0];
            g_yp[kc][(jb + 64) * 16 + tx + 8] = acc[1][1];
        }
        gbar();

        // ========== Phase C: reduce+bias+gelu fill, GEMM2 partial (8 nt x 16 kc2) ==========
        {
            const int nt = bid & 7, kc2 = bid >> 3;
            const int j0 = kc2 * 128;
            for (int i = tid; i < 128 * 16; i += 512) {
                int j = i >> 4, bp = i & 15;
                ull v = pdup(ba[j0 + j]);
#pragma unroll
                for (int p = 0; p < 8; p++) {
                    ull u = __ldcg(&g_yp[p][(j0 + j) * 16 + bp]);
                    ADD2(v, v, u);
                }
                float lo, hi;
                unpack2(v, lo, hi);
                lo = 0.5f * lo * (1.0f + erff(lo * 0.70710678118654752440f));
                hi = 0.5f * hi * (1.0f + erff(hi * 0.70710678118654752440f));
                smU[bp * 130 + j] = pack2(lo, hi);
            }
            ull acc[2][2] = {{0ull, 0ull}, {0ull, 0ull}};
            gemm_core<4, 130>(Wb + (size_t)(nt * 128) * 2048 + j0, smU, acc, tid, tx, ty);
            const int nb = nt * 128 + ty;
            g_y2p[kc2][nb * 16 + tx]            = acc[0][0];
            g_y2p[kc2][nb * 16 + tx + 8]        = acc[0][1];
            g_y2p[kc2][(nb + 64) * 16 + tx]     = acc[1][0];
            g_y2p[kc2][(nb + 64) * 16 + tx + 8] = acc[1][1];
        }
        gbar();

        // ========== Phase D: reduce + bias + LN + residual + out (16 blocks, b-pairs) =====
        if (bid < 16) {
            const int bp = bid;
            __shared__ ull redU[16];
            __shared__ ull shm[2];
            const int n0 = tid * 2;
            ull s0 = pdup(bb[n0]), s1 = pdup(bb[n0 + 1]);
#pragma unroll
            for (int kc = 0; kc < 16; kc++) {
                ull u0 = __ldcg(&g_y2p[kc][n0 * 16 + bp]);
                ull u1 = __ldcg(&g_y2p[kc][(n0 + 1) * 16 + bp]);
                ADD2(s0, s0, u0);
                ADD2(s1, s1, u1);
            }
            // mean (packed lanes = the two b's)
            ull ls;
            ADD2(ls, s0, s1);
            for (int o = 16; o; o >>= 1) {
                ull other = __shfl_xor_sync(0xffffffffu, ls, o);
                ADD2(ls, ls, other);
            }
            if ((tid & 31) == 0) redU[tid >> 5] = ls;
            __syncthreads();
            if (tid == 0) {
                ull tot = redU[0];
                for (int w = 1; w < 16; w++) ADD2(tot, tot, redU[w]);
                float slo, shi;
                unpack2(tot, slo, shi);
                shm[0] = pack2(-slo * (1.0f / 1024.0f), -shi * (1.0f / 1024.0f));
            }
            __syncthreads();
            const ull nmu = shm[0];
            ull d0, d1, q0, q1, ls2;
            ADD2(d0, s0, nmu);
            ADD2(d1, s1, nmu);
            MUL2(q0, d0, d0);
            MUL2(q1, d1, d1);
            ADD2(ls2, q0, q1);
            for (int o = 16; o; o >>= 1) {
                ull other = __shfl_xor_sync(0xffffffffu, ls2, o);
                ADD2(ls2, ls2, other);
            }
            if ((tid & 31) == 0) redU[tid >> 5] = ls2;
            __syncthreads();
            if (tid == 0) {
                ull tot = redU[0];
                for (int w = 1; w < 16; w++) ADD2(tot, tot, redU[w]);
                float slo, shi;
                unpack2(tot, slo, shi);
                shm[1] = pack2(rsqrtf(slo * (1.0f / 1024.0f) + 1e-5f),
                               rsqrtf(shi * (1.0f / 1024.0f) + 1e-5f));
            }
            __syncthreads();
            const ull rs2 = shm[1];
#pragma unroll
            for (int q = 0; q < 2; q++) {
                const int n = n0 + q;
                ull s = q ? s1 : s0;
                ull d = q ? d1 : d0;
                ull gd = pdup(gamma[n]), bd = pdup(beta[n]);
                ull tt2, base;
                MUL2(tt2, d, rs2);
                ADD2(base, bd, s);
                FMA2(base, tt2, gd);
                float lo, hi;
                unpack2(base, lo, hi);
                g_h[bp * CC + n] = lo;
                g_h[(bp + 16) * CC + n] = hi;
                out[((size_t)bp * TT + t) * CC + n] = lo;
                out[((size_t)(bp + 16) * TT + t) * CC + n] = hi;
            }
        }
        gbar();
    }
}

extern "C" void kernel_launch(void* const* d_in, const int* in_sizes, int n_in,
                              void* d_out, int out_size) {
    const float* x     = (const float*)d_in[0];
    const float* Wa    = (const float*)d_in[1];
    const float* ba    = (const float*)d_in[2];
    const float* Wb    = (const float*)d_in[3];
    const float* bb    = (const float*)d_in[4];
    const float* gamma = (const float*)d_in[5];
    const float* beta  = (const float*)d_in[6];
    float* out = (float*)d_out;

    const int smem = SMEM_ULL * 8;   // 102656 B
    cudaFuncSetAttribute(k_main, cudaFuncAttributeMaxDynamicSharedMemorySize, smem);
    k_main<<<NBLK, 512, smem>>>(x, Wa, ba, Wb, bb, gamma, beta, out);
}

// round 6
// speedup vs baseline: 1.5383x; 1.5383x over previous
#include <cuda_runtime.h>
#include <math.h>

// B=32, T=1024, C=1024, J=2048. One persistent kernel, 128 blocks x 512 thr.
// Scalar fp32 FFMA, 4j x 4b thread tile, conflict-free strided-b smem access.

#define BB 32
#define CC 1024
#define TT 1024
#define NBLK 128

// ---- scratch ----
__device__ __align__(16) float g_h[BB * CC];            // h[b][c]
__device__ __align__(16) float g_yp[16][2048 * 32];     // GEMM1 partials [kc][j][b]
__device__ __align__(16) float g_y2p[32][BB * CC];      // GEMM2 partials [kc2][b][n]

// ---- grid barrier ----
__device__ unsigned g_count = 0;
__device__ volatile unsigned g_gen = 0;

__device__ __forceinline__ void gbar() {
    __syncthreads();
    if (threadIdx.x == 0) {
        __threadfence();
        unsigned gen = g_gen;
        if (atomicAdd(&g_count, 1u) == NBLK - 1u) {
            atomicExch(&g_count, 0u);
            __threadfence();
            g_gen = gen + 1u;
        } else {
            while (g_gen == gen) __nanosleep(32);
        }
        __threadfence();
    }
    __syncthreads();
}

// smem (floats): zs [32][<=132] at 0 ; ws 2 x [256][36] at 4224
#define WOFF 4224
#define WSTR (256 * 36)
#define SMEM_FLOATS (WOFF + 2 * WSTR)   // 22656 floats = 90624 B

// Inner GEMM: 32-K stages, double-buffered weights.
// Thread (tx = tid&7, ty = tid>>3): j rows = ty*4+{0..3}, b = tx+8*{0..3}.
template <int NSTAGES, int ZSTR>
__device__ __forceinline__ void gemm_core(const float* __restrict__ wrow,
                                          float* sm, float acc[4][4],
                                          int tid, int tx, int ty) {
    float* zs = sm;
    float* wp = sm + WOFF;
    const int jf = tid >> 1, kh = (tid & 1) * 16;
    const float* wsrc = wrow + (size_t)jf * 2048 + kh;

    {   // stage 0 fill
        float4 f0 = *(const float4*)(wsrc);
        float4 f1 = *(const float4*)(wsrc + 4);
        float4 f2 = *(const float4*)(wsrc + 8);
        float4 f3 = *(const float4*)(wsrc + 12);
        float* wd = wp + jf * 36 + kh;
        *(float4*)(wd)      = f0;
        *(float4*)(wd + 4)  = f1;
        *(float4*)(wd + 8)  = f2;
        *(float4*)(wd + 12) = f3;
    }
    __syncthreads();

    int buf = 0;
#pragma unroll 1
    for (int ks = 0; ks < NSTAGES; ks++) {
        float4 p0, p1, p2, p3;
        if (ks + 1 < NSTAGES) {
            const float* wn = wsrc + (ks + 1) * 32;
            p0 = *(const float4*)(wn);
            p1 = *(const float4*)(wn + 4);
            p2 = *(const float4*)(wn + 8);
            p3 = *(const float4*)(wn + 12);
        }
        const float* wb = wp + buf * WSTR + (ty * 4) * 36;
        const float* zb = zs + tx * ZSTR + ks * 32;
#pragma unroll
        for (int kk = 0; kk < 8; kk++) {
            float4 wr[4], zr[4];
#pragma unroll
            for (int jj = 0; jj < 4; jj++)
                wr[jj] = *(const float4*)(wb + jj * 36 + kk * 4);
#pragma unroll
            for (int q = 0; q < 4; q++)
                zr[q] = *(const float4*)(zb + q * 8 * ZSTR + kk * 4);
#pragma unroll
            for (int jj = 0; jj < 4; jj++)
#pragma unroll
                for (int q = 0; q < 4; q++) {
                    acc[jj][q] += wr[jj].x * zr[q].x;
                    acc[jj][q] += wr[jj].y * zr[q].y;
                    acc[jj][q] += wr[jj].z * zr[q].z;
                    acc[jj][q] += wr[jj].w * zr[q].w;
                }
        }
        if (ks + 1 < NSTAGES) {
            float* wd = wp + (buf ^ 1) * WSTR + jf * 36 + kh;
            *(float4*)(wd)      = p0;
            *(float4*)(wd + 4)  = p1;
            *(float4*)(wd + 8)  = p2;
            *(float4*)(wd + 12) = p3;
        }
        __syncthreads();
        buf ^= 1;
    }
}

__global__ void __launch_bounds__(512, 1)
k_main(const float* __restrict__ x, const float* __restrict__ Wa,
       const float* __restrict__ ba, const float* __restrict__ Wb,
       const float* __restrict__ bb, const float* __restrict__ gamma,
       const float* __restrict__ beta, float* __restrict__ out) {
    extern __shared__ float sm[];
    const int bid = blockIdx.x, tid = threadIdx.x;
    const int tx = tid & 7, ty = tid >> 3;

    for (int i = bid * 512 + tid; i < BB * CC; i += NBLK * 512) g_h[i] = 0.0f;
    gbar();

    for (int t = 0; t < TT; t++) {
        // ===== Phase A: GEMM1 partial. 8 jt (256-wide) x 16 kc (128-K) =====
        {
            const int jt = bid & 7, kc = bid >> 3;
            // z fill: zs[b][132], K-chunk 128. kc<8 -> h, else x.
            {
                const int b = tid >> 4, k8 = (tid & 15) * 8;
                float4 v0, v1;
                if (kc < 8) {
                    const float* p = g_h + b * CC + kc * 128 + k8;
                    v0 = __ldcg((const float4*)p);
                    v1 = __ldcg((const float4*)(p + 4));
                } else {
                    const float* p = x + ((size_t)b * TT + t) * CC + (kc - 8) * 128 + k8;
                    v0 = *(const float4*)p;
                    v1 = *(const float4*)(p + 4);
                }
                *(float4*)&sm[b * 132 + k8]     = v0;
                *(float4*)&sm[b * 132 + k8 + 4] = v1;
            }
            float acc[4][4];
#pragma unroll
            for (int a = 0; a < 4; a++)
#pragma unroll
                for (int c = 0; c < 4; c++) acc[a][c] = 0.0f;
            gemm_core<4, 132>(Wa + (size_t)(jt * 256) * 2048 + kc * 128,
                              sm, acc, tid, tx, ty);
            const int jb = jt * 256 + ty * 4;
#pragma unroll
            for (int jj = 0; jj < 4; jj++)
#pragma unroll
                for (int q = 0; q < 4; q++)
                    g_yp[kc][(jb + jj) * 32 + tx + 8 * q] = acc[jj][q];
        }
        gbar();

        // ===== Phase C: gelu(reduce)+fill, GEMM2 partial. 4 nt x 32 kc2 (64-K) =====
        {
            const int nt = bid & 3, kc2 = bid >> 2;
            const int j0 = kc2 * 64;
            for (int i = tid; i < 64 * 32; i += 512) {
                int j = i >> 5, b = i & 31;
                float v = ba[j0 + j];
#pragma unroll
                for (int p = 0; p < 16; p++)
                    v += __ldcg(&g_yp[p][(j0 + j) * 32 + b]);
                v = 0.5f * v * (1.0f + erff(v * 0.70710678118654752440f));
                sm[b * 68 + j] = v;
            }
            float acc[4][4];
#pragma unroll
            for (int a = 0; a < 4; a++)
#pragma unroll
                for (int c = 0; c < 4; c++) acc[a][c] = 0.0f;
            gemm_core<2, 68>(Wb + (size_t)(nt * 256) * 2048 + j0,
                             sm, acc, tid, tx, ty);
            const int n0 = nt * 256 + ty * 4;
#pragma unroll
            for (int q = 0; q < 4; q++) {
                float4 v = make_float4(acc[0][q], acc[1][q], acc[2][q], acc[3][q]);
                *(float4*)&g_y2p[kc2][(tx + 8 * q) * 1024 + n0] = v;
            }
        }
        gbar();

        // ===== Phase D: reduce + bias + LN + residual + out. 32 blocks =====
        if (bid < 32) {
            const int b = bid;
            __shared__ float red[16];
            __shared__ float shm[2];
            const int n = tid * 2;
            float2 s = *(const float2*)(bb + n);
#pragma unroll
            for (int kc2 = 0; kc2 < 32; kc2++) {
                float2 p = __ldcg((const float2*)&g_y2p[kc2][b * 1024 + n]);
                s.x += p.x;
                s.y += p.y;
            }
            float ls = s.x + s.y;
            for (int o = 16; o; o >>= 1) ls += __shfl_xor_sync(~0u, ls, o);
            if ((tid & 31) == 0) red[tid >> 5] = ls;
            __syncthreads();
            if (tid == 0) {
                float tot = 0;
#pragma unroll
                for (int w = 0; w < 16; w++) tot += red[w];
                shm[0] = tot * (1.0f / 1024.0f);
            }
            __syncthreads();
            const float mu = shm[0];
            float d0 = s.x - mu, d1 = s.y - mu;
            float ls2 = d0 * d0 + d1 * d1;
            for (int o = 16; o; o >>= 1) ls2 += __shfl_xor_sync(~0u, ls2, o);
            if ((tid & 31) == 0) red[tid >> 5] = ls2;
            __syncthreads();
            if (tid == 0) {
                float tot = 0;
#pragma unroll
                for (int w = 0; w < 16; w++) tot += red[w];
                shm[1] = rsqrtf(tot * (1.0f / 1024.0f) + 1e-5f);
            }
            __syncthreads();
            const float rs = shm[1];
            float2 g2 = *(const float2*)(gamma + n);
            float2 b2 = *(const float2*)(beta + n);
            float2 hv;
            hv.x = d0 * rs * g2.x + b2.x + s.x;
            hv.y = d1 * rs * g2.y + b2.y + s.y;
            *(float2*)&g_h[b * CC + n] = hv;
            *(float2*)(out + ((size_t)b * TT + t) * CC + n) = hv;
        }
        gbar();
    }
}

extern "C" void kernel_launch(void* const* d_in, const int* in_sizes, int n_in,
                              void* d_out, int out_size) {
    const float* x     = (const float*)d_in[0];
    const float* Wa    = (const float*)d_in[1];
    const float* ba    = (const float*)d_in[2];
    const float* Wb    = (const float*)d_in[3];
    const float* bb    = (const float*)d_in[4];
    const float* gamma = (const float*)d_in[5];
    const float* beta  = (const float*)d_in[6];
    float* out = (float*)d_out;

    const int smem = SMEM_FLOATS * 4;   // 90624 B
    cudaFuncSetAttribute(k_main, cudaFuncAttributeMaxDynamicSharedMemorySize, smem);
    k_main<<<NBLK, 512, smem>>>(x, Wa, ba, Wb, bb, gamma, beta, out);
}